// round 17
// baseline (speedup 1.0000x reference)
#include <cuda_runtime.h>
#include <math_constants.h>

// Problem constants (fixed by the dataset shapes)
#define B_  2
#define H_  50
#define W_  50
#define C_  256
#define R_  100
#define PH 7
#define PW 7
#define C4V 64            // float4 per spatial position (256 ch / 4)

__device__ __forceinline__ float4 fmax4(float4 a, float4 b) {
    return make_float4(fmaxf(a.x, b.x), fmaxf(a.y, b.y),
                       fmaxf(a.z, b.z), fmaxf(a.w, b.w));
}

// One block per (b, roi, row_bin). Block = (32 lanes x 7 warps): warp j owns
// column bin j; each lane covers 8 channels (2 x LDG.128 per position).
// __launch_bounds__(224, 9) forces regs <= 32 so 9 blocks/SM are resident:
// grid 1400 / (148*9) = 1.05 waves — single-wave execution, 94% occupancy.
__global__ void __launch_bounds__(32 * PW, 9) roi_pool_kernel(
    const float* __restrict__ fm,     // (B, H, W, C)
    const float* __restrict__ rois,   // (B, R, 4)
    float* __restrict__ out)          // (B, R, PH, PW, C)
{
    const int blk  = blockIdx.x;
    const int bi   = blk % PH;                 // row bin
    const int r    = (blk / PH) % R_;
    const int b    = blk / (PH * R_);
    const int lane = threadIdx.x;              // 8-channel group
    const int j    = threadIdx.y;              // column bin (warp id)

    const float4 roi = *reinterpret_cast<const float4*>(rois + (size_t)(b * R_ + r) * 4);

    // Mirror reference: truncating cast of f32 products (all coords >= 0)
    const int hs = (int)(H_ * roi.x);
    const int ws = (int)(W_ * roi.y);
    const int he = (int)(H_ * roi.z);
    const int we = (int)(W_ * roi.w);

    const int sh = max((he - hs) / PH, 1);
    const int sw = max((we - ws) / PW, 1);

    // Row/col range for this bin. Last bin absorbs the remainder.
    const int y0 = hs + bi * sh;
    const int y1 = (bi == PH - 1) ? he : min(hs + (bi + 1) * sh, he);
    const int x0 = ws + j * sw;
    const int x1 = (j == PW - 1) ? we : min(ws + (j + 1) * sw, we);

    const float4* __restrict__ fmb =
        reinterpret_cast<const float4*>(fm + (size_t)b * H_ * W_ * C_) + lane * 2;

    const float4 NEG_INF4 = make_float4(-CUDART_INF_F, -CUDART_INF_F,
                                        -CUDART_INF_F, -CUDART_INF_F);
    // Two positions in flight, two float4 each -> 4 independent load chains.
    float4 aL = NEG_INF4, aH = NEG_INF4;
    float4 bL = NEG_INF4, bH = NEG_INF4;

    for (int y = y0; y < y1; ++y) {
        const float4* __restrict__ p = fmb + ((size_t)y * W_ + x0) * C4V;
        int x = x0;
        for (; x + 1 < x1; x += 2, p += 2 * C4V) {
            float4 v0L = __ldg(p);
            float4 v0H = __ldg(p + 1);
            float4 v1L = __ldg(p + C4V);
            float4 v1H = __ldg(p + C4V + 1);
            aL = fmax4(aL, v0L);
            aH = fmax4(aH, v0H);
            bL = fmax4(bL, v1L);
            bH = fmax4(bH, v1H);
        }
        if (x < x1) {
            aL = fmax4(aL, __ldg(p));
            aH = fmax4(aH, __ldg(p + 1));
        }
    }
    aL = fmax4(aL, bL);
    aH = fmax4(aH, bH);

    float4* __restrict__ o = reinterpret_cast<float4*>(
        out + ((((size_t)(b * R_ + r)) * PH + bi) * PW + j) * C_ + lane * 8);
    o[0] = aL;
    o[1] = aH;
}

extern "C" void kernel_launch(void* const* d_in, const int* in_sizes, int n_in,
                              void* d_out, int out_size)
{
    const float* fm   = (const float*)d_in[0];   // feature_map (2,50,50,256)
    const float* rois = (const float*)d_in[1];   // rois (2,100,4)
    float* out = (float*)d_out;                  // (2,100,7,7,256)

    (void)in_sizes; (void)n_in; (void)out_size;

    dim3 grid(B_ * R_ * PH);
    dim3 block(32, PW);
    roi_pool_kernel<<<grid, block>>>(fm, rois, out);
}